// round 14
// baseline (speedup 1.0000x reference)
#include <cuda_runtime.h>
#include <cuda_bf16.h>
#include <math.h>

#define BATCH 128
#define TLEN  2048
#define CH    128
#define EDIM  32
#define HDIM  64
#define PRED  336

typedef unsigned long long ull;

// scratch (allocation-free rule: __device__ globals)
__device__ __align__(16) float g_v[BATCH * EDIM];          // encoder output v
__device__ __align__(16) float g_Mh[HDIM * HDIM];          // (Wo*Wh)^T rows
__device__ __align__(16) float g_Mg[HDIM * HDIM];
__device__ __align__(16) float g_ch[HDIM];
__device__ __align__(16) float g_cg[HDIM];
__device__ __align__(16) float g_Qt[CH * HDIM];            // (Wo*Wr) transposed: [c][j]
__device__ __align__(16) float g_cvec[CH];                 // bdo*Wr

// ---- packed f32x2 helpers (Blackwell) --------------------------------------
__device__ __forceinline__ ull fma2v(ull a, ull b, ull c) {
    ull d; asm("fma.rn.f32x2 %0, %1, %2, %3;" : "=l"(d) : "l"(a), "l"(b), "l"(c));
    return d;
}
__device__ __forceinline__ ull addx2(ull a, ull b) {
    ull d; asm("add.rn.f32x2 %0, %1, %2;" : "=l"(d) : "l"(a), "l"(b));
    return d;
}
__device__ __forceinline__ float2 unpk(ull v) {
    float2 r; asm("mov.b64 {%0, %1}, %2;" : "=f"(r.x), "=f"(r.y) : "l"(v));
    return r;
}
__device__ __forceinline__ ull pk(float lo, float hi) {
    ull v; asm("mov.b64 %0, {%1, %2};" : "=l"(v) : "f"(lo), "f"(hi));
    return v;
}
__device__ __forceinline__ ull pk1(float v) {
    ull r; asm("mov.b64 %0, {%1, %1};" : "=l"(r) : "f"(v));
    return r;
}

// ---------------------------------------------------------------------------
// Kernel A: 2 batch rows per block, 512 threads, quarter-T GEMV split.
// 2x warps + half the serial per-thread load chain vs R13 (latency-bound fix).
// ---------------------------------------------------------------------------
__global__ void __launch_bounds__(512, 1) ka_encoder(
    const float* __restrict__ x,
    const float* __restrict__ Wt, const float* __restrict__ bt,
    const float* __restrict__ Ww, const float* __restrict__ bw,
    const float* __restrict__ Wdm, const float* __restrict__ bdm,
    const float* __restrict__ Wre, const float* __restrict__ bre)
{
    int b0 = blockIdx.x * 2;
    int tid = threadIdx.x;

    __shared__ __align__(16) ull sRaw[TLEN];   // packed (row0,row1); later residual
    __shared__ __align__(16) ull sT[TLEN];     // packed trend
    ull*   part = sRaw;                        // overlay after GEMV (512 ull)
    float* sAcc = (float*)(sRaw + 512);

    const float* xa = x + (size_t)b0 * TLEN * CH;
    const float* xb = xa + (size_t)TLEN * CH;
    for (int t = tid; t < TLEN; t += 512)
        sRaw[t] = pk(xa[(size_t)t * CH], xb[(size_t)t * CH]);
    __syncthreads();

    for (int t = tid; t < TLEN; t += 512) {
        float sa = 0.f, sb = 0.f;
        #pragma unroll
        for (int d = -3; d <= 3; d++) {
            int u = t + d; u = min(max(u, 0), TLEN - 1);
            float2 q = unpk(sRaw[u]);
            sa += q.x; sb += q.y;
        }
        sT[t] = pk(sa / 7.0f, sb / 7.0f);
    }
    __syncthreads();

    {
        const ull negone = pk1(-1.0f);
        for (int t = tid; t < TLEN; t += 512)
            sRaw[t] = fma2v(sT[t], negone, sRaw[t]);
    }
    __syncthreads();

    int e = tid & 31;
    int m = (tid >> 5) & 3;      // 0: trend, 1..3: residual signals
    int quar = tid >> 7;         // 0..3
    const float* W = (m == 0) ? Wt : (m == 1) ? Ww : (m == 2) ? Wdm : Wre;
    const ull* sig = (m == 0) ? sT : sRaw;
    int tb = quar * (TLEN / 4);

    ull a0 = 0, a1 = 0, a2 = 0, a3 = 0;
    for (int t = tb; t < tb + TLEN / 4; t += 16) {
        float wv[16];
        #pragma unroll
        for (int u = 0; u < 16; u++) wv[u] = W[(t + u) * EDIM + e];
        #pragma unroll
        for (int u = 0; u < 16; u += 4) {
            a0 = fma2v(sig[t + u + 0], pk1(wv[u + 0]), a0);
            a1 = fma2v(sig[t + u + 1], pk1(wv[u + 1]), a1);
            a2 = fma2v(sig[t + u + 2], pk1(wv[u + 2]), a2);
            a3 = fma2v(sig[t + u + 3], pk1(wv[u + 3]), a3);
        }
    }
    ull mine = addx2(addx2(a0, a1), addx2(a2, a3));
    __syncthreads();                 // GEMV reads done before part overlay
    part[tid] = mine;
    __syncthreads();
    if (tid < 128) {
        ull q4 = addx2(addx2(part[tid], part[tid + 128]),
                       addx2(part[tid + 256], part[tid + 384]));
        float2 q = unpk(q4);
        const float* be = (m == 0) ? bt : (m == 1) ? bw : (m == 2) ? bdm : bre;
        float bias = be[e];
        sAcc[(0 * 4 + m) * EDIM + e] = tanhf(q.x + bias);
        sAcc[(1 * 4 + m) * EDIM + e] = tanhf(q.y + bias);
    }
    __syncthreads();
    if (tid < 64) {
        int r = tid >> 5, e2 = tid & 31;
        const float* a = sAcc + r * 4 * EDIM;
        g_v[(b0 + r) * EDIM + e2] =
            ((a[0 * EDIM + e2] + a[1 * EDIM + e2]) + a[2 * EDIM + e2]) + a[3 * EDIM + e2];
    }
}

// ---------------------------------------------------------------------------
// Kernel W (prep): M_h = Wo*Wh, M_g = Wo*Wg, Qt = (Wo*Wr)^T, c-vectors.
// ---------------------------------------------------------------------------
__global__ void __launch_bounds__(128) kw_prep(
    const float* __restrict__ Wh, const float* __restrict__ Wg,
    const float* __restrict__ Wo, const float* __restrict__ bdo,
    const float* __restrict__ Wr)
{
    int j = blockIdx.x;     // 0..63
    int t = threadIdx.x;    // 0..127

    if (t < HDIM) {
        float mh = 0.f, mg = 0.f;
        #pragma unroll 8
        for (int e = 0; e < EDIM; e++) {
            float wo = Wo[t * EDIM + e];
            mh = fmaf(wo, Wh[e * HDIM + j], mh);
            mg = fmaf(wo, Wg[e * HDIM + j], mg);
        }
        g_Mh[j * HDIM + t] = mh;
        g_Mg[j * HDIM + t] = mg;
    }
    {
        float q = 0.f;
        #pragma unroll 8
        for (int e = 0; e < EDIM; e++)
            q = fmaf(Wo[j * EDIM + e], Wr[e * CH + t], q);
        g_Qt[t * HDIM + j] = q;                  // transposed: row per channel
    }
    if (j == 0) {
        float cv = 0.f;
        #pragma unroll 8
        for (int e = 0; e < EDIM; e++)
            cv = fmaf(bdo[e], Wr[e * CH + t], cv);
        g_cvec[t] = cv;
    }
    if (t == 0) {
        float chv = 0.f;
        for (int e = 0; e < EDIM; e++) chv = fmaf(bdo[e], Wh[e * HDIM + j], chv);
        g_ch[j] = chv;
    }
    if (t == 1) {
        float cgv = 0.f;
        for (int e = 0; e < EDIM; e++) cgv = fmaf(bdo[e], Wg[e * HDIM + j], cgv);
        g_cg[j] = cgv;
    }
}

// ---------------------------------------------------------------------------
// Kernel B (FUSED, warp-specialized): 256 threads/row.
// Threads 0-127: the 336-step (H,G) scan exactly as R13 (critical path).
// Threads 128-255: projection warps — own channel c, Qt column in registers,
// consume sUa[p] after the shared per-step barrier. Double buffering makes the
// single uniform __syncthreads per step sufficient for both roles.
// ---------------------------------------------------------------------------
__global__ void __launch_bounds__(256, 1) kb_scan(
    const float* __restrict__ Wh, const float* __restrict__ bh,
    const float* __restrict__ Wg, const float* __restrict__ bg,
    const float* __restrict__ Wr, const float* __restrict__ br,
    float* __restrict__ out)
{
    int b = blockIdx.x;
    int t = threadIdx.x;            // 256 threads
    bool isProj = (t >= 128);

    __shared__ __align__(16) float sU[2][HDIM];
    __shared__ __align__(16) float sUa[2][HDIM];

    // ---- scan-role registers ----
    int j = (t & 127) >> 1;
    int h = t & 1;
    float SH = 0.f, SG = 0.f, chv = 0.f, cgv = 0.f, Uacc = 0.f;
    ull Mh16[16], Mg16[16];

    // ---- proj-role registers ----
    int c = t - 128;
    float basec = 0.f, cvc = 0.f;
    ull Qc[32];
    float* outb = out + (size_t)b * PRED * CH + (isProj ? c : 0);

    if (!isProj) {
        SH = bh[j]; SG = bg[j];
        #pragma unroll 8
        for (int e = 0; e < EDIM; e++) {
            float ve = g_v[b * EDIM + e];
            SH = fmaf(ve, Wh[e * HDIM + j], SH);
            SG = fmaf(ve, Wg[e * HDIM + j], SG);
        }
        const float* mh = g_Mh + j * HDIM + h * 32;
        const float* mg = g_Mg + j * HDIM + h * 32;
        #pragma unroll
        for (int k = 0; k < 16; k++) {
            Mh16[k] = pk(mh[2 * k], mh[2 * k + 1]);
            Mg16[k] = pk(mg[2 * k], mg[2 * k + 1]);
        }
        chv = g_ch[j];
        cgv = g_cg[j];
    } else {
        basec = br[c];
        #pragma unroll 8
        for (int e = 0; e < EDIM; e++)
            basec = fmaf(g_v[b * EDIM + e], Wr[e * CH + c], basec);
        const float4* qp = (const float4*)(g_Qt + c * HDIM);
        #pragma unroll
        for (int m = 0; m < 16; m++) {
            float4 f = qp[m];
            Qc[2 * m]     = pk(f.x, f.y);
            Qc[2 * m + 1] = pk(f.z, f.w);
        }
        cvc = g_cvec[c];
    }
    int p = 0;
    __syncthreads();

    for (int s = 0; s < PRED; s++) {
        if (!isProj) {
            float sigH = __fdividef(1.0f, 1.0f + __expf(-SH));
            float sigG = __fdividef(1.0f, 1.0f + __expf(-SG));
            float u = (SH * sigH) * sigG;
            if (h == 0) {
                Uacc += u;
                sU[p][j]  = u;
                sUa[p][j] = Uacc;
            }
        }
        __syncthreads();

        if (!isProj) {
            // ---- scan dot: half-range j' in [32h, 32h+32) ----
            const float4* ub = ((const float4*)sU[p]) + h * 8;
            ull aH0 = 0, aH1 = 0, aG0 = 0, aG1 = 0;
            #pragma unroll
            for (int k = 0; k < 8; k++) {
                float4 f = ub[k];
                ull u0 = pk(f.x, f.y);
                ull u1 = pk(f.z, f.w);
                aH0 = fma2v(u0, Mh16[2 * k],     aH0);
                aH1 = fma2v(u1, Mh16[2 * k + 1], aH1);
                aG0 = fma2v(u0, Mg16[2 * k],     aG0);
                aG1 = fma2v(u1, Mg16[2 * k + 1], aG1);
            }
            float2 qh = unpk(addx2(aH0, aH1));
            float2 qg = unpk(addx2(aG0, aG1));
            float dH = qh.x + qh.y;
            float dG = qg.x + qg.y;
            dH += __shfl_xor_sync(0xffffffffu, dH, 1);
            dG += __shfl_xor_sync(0xffffffffu, dG, 1);
            SH += dH + chv;
            SG += dG + cgv;
        } else {
            // ---- projection on dedicated warps: out[b,s,c] ----
            const float4* ua = (const float4*)sUa[p];
            ull a0 = 0, a1 = 0, a2 = 0, a3 = 0;
            #pragma unroll
            for (int m = 0; m < 16; m += 2) {
                float4 f0 = ua[m];
                float4 f1 = ua[m + 1];
                a0 = fma2v(pk(f0.x, f0.y), Qc[2 * m],     a0);
                a1 = fma2v(pk(f0.z, f0.w), Qc[2 * m + 1], a1);
                a2 = fma2v(pk(f1.x, f1.y), Qc[2 * m + 2], a2);
                a3 = fma2v(pk(f1.z, f1.w), Qc[2 * m + 3], a3);
            }
            float2 q = unpk(addx2(addx2(a0, a1), addx2(a2, a3)));
            outb[(size_t)s * CH] = fmaf((float)(s + 1), cvc, basec + (q.x + q.y));
        }
        p ^= 1;
    }
}

// ---------------------------------------------------------------------------
extern "C" void kernel_launch(void* const* d_in, const int* in_sizes, int n_in,
                              void* d_out, int out_size)
{
    const float* x        = (const float*)d_in[0];
    const float* We_trend = (const float*)d_in[1];
    const float* be_trend = (const float*)d_in[2];
    const float* We_weekly= (const float*)d_in[3];
    const float* be_weekly= (const float*)d_in[4];
    const float* We_daily = (const float*)d_in[5];
    const float* be_daily = (const float*)d_in[6];
    const float* We_resid = (const float*)d_in[7];
    const float* be_resid = (const float*)d_in[8];
    const float* Wd_in    = (const float*)d_in[9];
    const float* bd_in    = (const float*)d_in[10];
    const float* Wd_gate  = (const float*)d_in[11];
    const float* bd_gate  = (const float*)d_in[12];
    const float* Wd_out   = (const float*)d_in[13];
    const float* bd_out   = (const float*)d_in[14];
    const float* Wr       = (const float*)d_in[15];
    const float* br       = (const float*)d_in[16];
    float* out = (float*)d_out;

    ka_encoder<<<BATCH / 2, 512>>>(x, We_trend, be_trend, We_weekly, be_weekly,
                                   We_daily, be_daily, We_resid, be_resid);
    kw_prep<<<HDIM, 128>>>(Wd_in, Wd_gate, Wd_out, bd_out, Wr);
    kb_scan<<<BATCH, 256>>>(Wd_in, bd_in, Wd_gate, bd_gate, Wr, br, out);
}